// round 3
// baseline (speedup 1.0000x reference)
#include <cuda_runtime.h>
#include <cstddef>

// Problem constants (fixed by the reference)
#define BB 8
#define DD 32
#define NPIX 262144          // 512*512
#define KK 16

// Pass-1 tiling: 128 pixel-blocks x 2 d-groups x 8 images = 2048 blocks
#define P1_CHUNK  2048
#define P1_BLOCKS (NPIX / P1_CHUNK)    // 128

// Pass-2 tiling: one float4 (4 pixels) per thread
#define P2_TPB    256
#define P2_BLOCKS (NPIX / 4 / P2_TPB)  // 256 blocks per image

// Scratch (no cudaMalloc allowed)
__device__ float g_sums[BB * KK * DD];
__device__ float g_counts[BB * KK];
__device__ float g_means[BB * KK * DD];

// ---------------------------------------------------------------------------
// Zero scratch + output (graph replays re-enter with dirty state)
// ---------------------------------------------------------------------------
__global__ void k_zero(float* out) {
    int tid = threadIdx.x;
    for (int j = tid; j < BB * KK * DD; j += blockDim.x) g_sums[j] = 0.0f;
    if (tid < BB * KK) g_counts[tid] = 0.0f;
    if (tid == 0) out[0] = 0.0f;
}

// ---------------------------------------------------------------------------
// Pass 1: per-image segment sums (sums[K][D]) and counts[K].
// Block = 512 threads = 16 warps; warp w owns feature d = dg*16 + w.
// Each lane processes TWO float4s per iteration (independent LDGs -> MLP).
// Per-lane privatized smem bins: LDS/FADD/STS chains are conflict-free.
// ---------------------------------------------------------------------------
__global__ __launch_bounds__(512) void k_pass1(const float* __restrict__ emb,
                                               const int* __restrict__ gt) {
    __shared__ float acc[16 * KK * 32];          // [w][k][lane]  32 KB
    __shared__ float cnt[KK * 32];               // [k][lane]      2 KB
    __shared__ uchar4 lab4[P1_CHUNK / 4];        //                2 KB

    const int b  = blockIdx.z;
    const int dg = blockIdx.y;                   // d group: 0 or 1
    const int p0 = blockIdx.x * P1_CHUNK;
    const int tid = threadIdx.x;
    const int w   = tid >> 5;
    const int lane = tid & 31;
    const int d = dg * 16 + w;

    for (int j = tid; j < 16 * KK * 32; j += 512) acc[j] = 0.0f;
    if (tid < KK * 32) cnt[tid] = 0.0f;

    // Stage labels once (int4 -> uchar4): 512 entries, one per thread
    const int4* g4 = (const int4*)(gt + (size_t)b * NPIX + p0);
    for (int j = tid; j < P1_CHUNK / 4; j += 512) {
        int4 t = g4[j];
        lab4[j] = make_uchar4((unsigned char)t.x, (unsigned char)t.y,
                              (unsigned char)t.z, (unsigned char)t.w);
    }
    __syncthreads();

    const float4* e4 = (const float4*)(emb + ((size_t)(b * DD + d)) * NPIX + p0);
    const bool docnt = (dg == 0) && (w == 0);

    float* aw = acc + (w * KK) * 32 + lane;
    float* cw = cnt + lane;

    // 512 float4s per block-chunk; lane handles 16, two per iteration.
    #pragma unroll 4
    for (int i = 0; i < 8; i++) {
        int idx = i * 64 + lane;
        float4 va = __ldcs(&e4[idx]);
        float4 vb = __ldcs(&e4[idx + 32]);
        uchar4 ka = lab4[idx];
        uchar4 kb = lab4[idx + 32];
        aw[(int)ka.x * 32] += va.x;
        aw[(int)ka.y * 32] += va.y;
        aw[(int)ka.z * 32] += va.z;
        aw[(int)ka.w * 32] += va.w;
        aw[(int)kb.x * 32] += vb.x;
        aw[(int)kb.y * 32] += vb.y;
        aw[(int)kb.z * 32] += vb.z;
        aw[(int)kb.w * 32] += vb.w;
        if (docnt) {
            cw[(int)ka.x * 32] += 1.0f;
            cw[(int)ka.y * 32] += 1.0f;
            cw[(int)ka.z * 32] += 1.0f;
            cw[(int)ka.w * 32] += 1.0f;
            cw[(int)kb.x * 32] += 1.0f;
            cw[(int)kb.y * 32] += 1.0f;
            cw[(int)kb.z * 32] += 1.0f;
            cw[(int)kb.w * 32] += 1.0f;
        }
    }
    __syncthreads();

    // Reduce each (k) row across lanes, one atomicAdd per (b,k,d) per block.
    for (int k = 0; k < KK; k++) {
        float v = acc[(w * KK + k) * 32 + lane];
        #pragma unroll
        for (int off = 16; off; off >>= 1)
            v += __shfl_down_sync(0xffffffffu, v, off);
        if (lane == 0) atomicAdd(&g_sums[(b * KK + k) * DD + d], v);
    }
    if (docnt) {
        for (int k = 0; k < KK; k++) {
            float v = cnt[k * 32 + lane];
            #pragma unroll
            for (int off = 16; off; off >>= 1)
                v += __shfl_down_sync(0xffffffffu, v, off);
            if (lane == 0) atomicAdd(&g_counts[b * KK + k], v);
        }
    }
}

// ---------------------------------------------------------------------------
// Finalize: means, pairwise push loss, regularization. One block per image.
// ---------------------------------------------------------------------------
__global__ __launch_bounds__(256) void k_finalize(float* out) {
    __shared__ float m[KK * 33];    // padded means
    __shared__ float cs[KK];
    __shared__ float red[256];

    const int b = blockIdx.x;
    const int tid = threadIdx.x;

    if (tid < KK) cs[tid] = fmaxf(g_counts[b * KK + tid], 1.0f);
    __syncthreads();

    for (int j = tid; j < KK * DD; j += 256) {
        int k = j / DD, d = j % DD;
        float mean = g_sums[(b * KK + k) * DD + d] / cs[k];
        g_means[(b * KK + k) * DD + d] = mean;
        m[k * 33 + d] = mean;
    }
    __syncthreads();

    // Pairwise hinge on cluster-mean distances: thread -> (i,j), upper tri only.
    const int i = tid >> 4;
    const int j = tid & 15;
    float contrib = 0.0f;
    if (j > i) {
        float d2 = 0.0f;
        #pragma unroll
        for (int d = 0; d < DD; d++) {
            float df = m[i * 33 + d] - m[j * 33 + d];
            d2 = fmaf(df, df, d2);
        }
        float pd = sqrtf(d2);             // i<j: diagonal eye irrelevant
        float h = fmaxf(3.0f - pd, 0.0f); // 2 * DIST_THETA = 3.0
        contrib = h * h;
    }

    float reg = 0.0f;
    if (tid < KK) {
        float n2 = 0.0f;
        #pragma unroll
        for (int d = 0; d < DD; d++) {
            float v = m[tid * 33 + d];
            n2 = fmaf(v, v, n2);
        }
        reg = sqrtf(n2);
    }

    red[tid] = contrib * (1.0f / (KK * (KK - 1))) + 0.001f * reg * (1.0f / KK);
    __syncthreads();
    for (int off = 128; off; off >>= 1) {
        if (tid < off) red[tid] += red[tid + off];
        __syncthreads();
    }
    if (tid == 0) atomicAdd(out, red[0] * (1.0f / BB));
}

// ---------------------------------------------------------------------------
// Pass 2: per-pixel hinge variance loss, folded directly into the scalar.
// One float4 (4 consecutive pixels) per thread. d-loop in 4 groups of 8
// explicitly batched LDG.128s -> MLP_p1 ~ 8.
// ---------------------------------------------------------------------------
__global__ __launch_bounds__(P2_TPB) void k_pass2(const float* __restrict__ emb,
                                                  const int* __restrict__ gt,
                                                  float* out) {
    __shared__ float m[KK * 33];
    __shared__ float wk[KK];
    __shared__ float red[P2_TPB / 32];

    const int b  = blockIdx.y;
    const int tid = threadIdx.x;
    const int lane = tid & 31;
    const int w = tid >> 5;
    const int p4 = blockIdx.x * P2_TPB + tid;    // float4 index

    for (int j = tid; j < KK * DD; j += P2_TPB)
        m[(j / DD) * 33 + (j % DD)] = g_means[b * KK * DD + j];
    if (tid < KK)
        wk[tid] = 1.0f / ((float)KK * fmaxf(g_counts[b * KK + tid], 1.0f));
    __syncthreads();

    const float4* e4 = (const float4*)(emb + (size_t)b * DD * NPIX);
    const int4 kk = ((const int4*)(gt + (size_t)b * NPIX))[p4];

    const float* m0 = m + kk.x * 33;
    const float* m1 = m + kk.y * 33;
    const float* m2 = m + kk.z * 33;
    const float* m3 = m + kk.w * 33;

    float a0 = 0.0f, a1 = 0.0f, a2 = 0.0f, a3 = 0.0f;
    #pragma unroll
    for (int g = 0; g < 4; g++) {
        float4 v[8];
        #pragma unroll
        for (int j = 0; j < 8; j++)
            v[j] = __ldcs(&e4[(size_t)(g * 8 + j) * (NPIX / 4) + p4]);
        #pragma unroll
        for (int j = 0; j < 8; j++) {
            const int d = g * 8 + j;
            float t;
            t = v[j].x - m0[d]; a0 = fmaf(t, t, a0);
            t = v[j].y - m1[d]; a1 = fmaf(t, t, a1);
            t = v[j].z - m2[d]; a2 = fmaf(t, t, a2);
            t = v[j].w - m3[d]; a3 = fmaf(t, t, a3);
        }
    }

    float h, lacc = 0.0f;
    h = fmaxf(sqrtf(a0) - 0.5f, 0.0f); lacc = fmaf(h * h, wk[kk.x], lacc);
    h = fmaxf(sqrtf(a1) - 0.5f, 0.0f); lacc = fmaf(h * h, wk[kk.y], lacc);
    h = fmaxf(sqrtf(a2) - 0.5f, 0.0f); lacc = fmaf(h * h, wk[kk.z], lacc);
    h = fmaxf(sqrtf(a3) - 0.5f, 0.0f); lacc = fmaf(h * h, wk[kk.w], lacc);

    #pragma unroll
    for (int off = 16; off; off >>= 1)
        lacc += __shfl_down_sync(0xffffffffu, lacc, off);
    if (lane == 0) red[w] = lacc;
    __syncthreads();
    if (tid == 0) {
        float s = 0.0f;
        #pragma unroll
        for (int i = 0; i < P2_TPB / 32; i++) s += red[i];
        atomicAdd(out, s * (1.0f / BB));
    }
}

// ---------------------------------------------------------------------------
extern "C" void kernel_launch(void* const* d_in, const int* in_sizes, int n_in,
                              void* d_out, int out_size) {
    int ei = 0, gi = 1;
    // Defensive: identify inputs by size (embeddings = 67108864, gt = 2097152)
    if (n_in >= 2 && in_sizes[0] == BB * NPIX) { ei = 1; gi = 0; }

    const float* emb = (const float*)d_in[ei];
    const int*   gt  = (const int*)d_in[gi];
    float* out = (float*)d_out;

    k_zero<<<1, 512>>>(out);
    k_pass1<<<dim3(P1_BLOCKS, 2, BB), 512>>>(emb, gt);
    k_finalize<<<BB, 256>>>(out);
    k_pass2<<<dim3(P2_BLOCKS, BB), P2_TPB>>>(emb, gt, out);
}

// round 4
// speedup vs baseline: 1.1382x; 1.1382x over previous
#include <cuda_runtime.h>
#include <cstddef>

// Problem constants (fixed by the reference)
#define BB 8
#define DD 32
#define NPIX 262144          // 512*512
#define KK 16

// Pass-1 tiling: 32 pixel-chunks x 2 d-groups x 8 images = 512 blocks
#define P1_CHUNK  8192
#define P1_NCHUNK (NPIX / P1_CHUNK)    // 32

// Pass-2 tiling: one float4 (4 pixels) per thread
#define P2_TPB    256
#define P2_BLOCKS (NPIX / 4 / P2_TPB)  // 256 blocks per image

// Scratch (no cudaMalloc allowed). g_part/g_cntp are fully overwritten each
// launch -> no zeroing kernel needed.
__device__ float g_part[BB * P1_NCHUNK * KK * DD];   // per-chunk partial sums
__device__ float g_cntp[BB * P1_NCHUNK * KK];        // per-chunk partial counts
__device__ float g_counts[BB * KK];
__device__ float g_means[BB * KK * DD];

// ---------------------------------------------------------------------------
// Pass 1: per-image, per-chunk partial segment sums.
// Block = 512 threads = 16 warps; warp w owns plane d = dg*16 + w over the
// whole 8192-px chunk (64 float4 per lane -> epilogue amortized to ~3%).
// Per-lane privatized smem bins (stride 32): LDS/FADD/STS conflict-free.
// ---------------------------------------------------------------------------
__global__ __launch_bounds__(512) void k_pass1(const float* __restrict__ emb,
                                               const int* __restrict__ gt,
                                               float* out) {
    __shared__ float acc[16 * KK * 32];          // [w][k][lane]  32 KB
    __shared__ float cnt[KK * 32];               // [k][lane]      2 KB
    __shared__ uchar4 lab4[P1_CHUNK / 4];        //                8 KB

    const int b  = blockIdx.z;
    const int dg = blockIdx.y;                   // d group: 0 or 1
    const int c  = blockIdx.x;                   // chunk
    const int p0 = c * P1_CHUNK;
    const int tid = threadIdx.x;
    const int w   = tid >> 5;
    const int lane = tid & 31;
    const int d = dg * 16 + w;

    if (b == 0 && dg == 0 && c == 0 && tid == 0) out[0] = 0.0f;

    for (int j = tid; j < 16 * KK * 32; j += 512) acc[j] = 0.0f;
    if (tid < KK * 32) cnt[tid] = 0.0f;

    // Stage labels once (int4 -> uchar4): 2048 entries
    const int4* g4 = (const int4*)(gt + (size_t)b * NPIX + p0);
    for (int j = tid; j < P1_CHUNK / 4; j += 512) {
        int4 t = g4[j];
        lab4[j] = make_uchar4((unsigned char)t.x, (unsigned char)t.y,
                              (unsigned char)t.z, (unsigned char)t.w);
    }
    __syncthreads();

    const float4* e4 = (const float4*)(emb + ((size_t)(b * DD + d)) * NPIX + p0);
    const bool docnt = (dg == 0) && (w == 0);

    float* aw = acc + (w * KK) * 32 + lane;
    float* cw = cnt + lane;

    // 2048 float4s per plane-chunk per warp; 64 per lane, two per iteration.
    #pragma unroll 4
    for (int i = 0; i < 32; i++) {
        int idx = i * 64 + lane;
        float4 va = __ldcs(&e4[idx]);
        float4 vb = __ldcs(&e4[idx + 32]);
        uchar4 ka = lab4[idx];
        uchar4 kb = lab4[idx + 32];
        aw[(int)ka.x * 32] += va.x;
        aw[(int)ka.y * 32] += va.y;
        aw[(int)ka.z * 32] += va.z;
        aw[(int)ka.w * 32] += va.w;
        aw[(int)kb.x * 32] += vb.x;
        aw[(int)kb.y * 32] += vb.y;
        aw[(int)kb.z * 32] += vb.z;
        aw[(int)kb.w * 32] += vb.w;
        if (docnt) {
            cw[(int)ka.x * 32] += 1.0f;
            cw[(int)ka.y * 32] += 1.0f;
            cw[(int)ka.z * 32] += 1.0f;
            cw[(int)ka.w * 32] += 1.0f;
            cw[(int)kb.x * 32] += 1.0f;
            cw[(int)kb.y * 32] += 1.0f;
            cw[(int)kb.z * 32] += 1.0f;
            cw[(int)kb.w * 32] += 1.0f;
        }
    }
    __syncwarp();

    // Epilogue: rows acc[w][k][0..31] are contiguous 128B. 2 lanes per k-row,
    // each reads 4 float4, sum, 1 shuffle, STG (no atomics).
    {
        const int k = lane >> 1;
        const int h = lane & 1;
        const float4* row = (const float4*)(acc + ((w * KK + k) << 5) + (h << 4));
        float4 r0 = row[0], r1 = row[1], r2 = row[2], r3 = row[3];
        float s = ((r0.x + r0.y) + (r0.z + r0.w)) + ((r1.x + r1.y) + (r1.z + r1.w))
                + ((r2.x + r2.y) + (r2.z + r2.w)) + ((r3.x + r3.y) + (r3.z + r3.w));
        s += __shfl_down_sync(0xffffffffu, s, 1);
        if (h == 0)
            g_part[(((b * P1_NCHUNK + c) * KK + k) * DD) + d] = s;
    }
    if (docnt) {
        const int k = lane >> 1;
        const int h = lane & 1;
        const float4* row = (const float4*)(cnt + (k << 5) + (h << 4));
        float4 r0 = row[0], r1 = row[1], r2 = row[2], r3 = row[3];
        float s = ((r0.x + r0.y) + (r0.z + r0.w)) + ((r1.x + r1.y) + (r1.z + r1.w))
                + ((r2.x + r2.y) + (r2.z + r2.w)) + ((r3.x + r3.y) + (r3.z + r3.w));
        s += __shfl_down_sync(0xffffffffu, s, 1);
        if (h == 0)
            g_cntp[(b * P1_NCHUNK + c) * KK + k] = s;
    }
}

// ---------------------------------------------------------------------------
// Finalize: reduce partials -> counts & means; pairwise push loss; reg loss.
// One block per image.
// ---------------------------------------------------------------------------
__global__ __launch_bounds__(256) void k_finalize(float* out) {
    __shared__ float m[KK * 33];    // padded means
    __shared__ float cs[KK];
    __shared__ float red[256];

    const int b = blockIdx.x;
    const int tid = threadIdx.x;

    if (tid < KK) {
        float s = 0.0f;
        #pragma unroll 4
        for (int c = 0; c < P1_NCHUNK; c++)
            s += g_cntp[(b * P1_NCHUNK + c) * KK + tid];
        float cv = fmaxf(s, 1.0f);
        cs[tid] = cv;
        g_counts[b * KK + tid] = cv;
    }
    __syncthreads();

    for (int j = tid; j < KK * DD; j += 256) {
        int k = j >> 5, d = j & 31;
        float s = 0.0f;
        #pragma unroll 4
        for (int c = 0; c < P1_NCHUNK; c++)
            s += g_part[(((b * P1_NCHUNK + c) * KK + k) * DD) + d];
        float mean = s / cs[k];
        g_means[(b * KK + k) * DD + d] = mean;
        m[k * 33 + d] = mean;
    }
    __syncthreads();

    // Pairwise hinge on cluster-mean distances: thread -> (i,j), upper tri only.
    const int i = tid >> 4;
    const int j = tid & 15;
    float contrib = 0.0f;
    if (j > i) {
        float d2 = 0.0f;
        #pragma unroll
        for (int d = 0; d < DD; d++) {
            float df = m[i * 33 + d] - m[j * 33 + d];
            d2 = fmaf(df, df, d2);
        }
        float pd = sqrtf(d2);             // i<j: diagonal eye irrelevant
        float h = fmaxf(3.0f - pd, 0.0f); // 2 * DIST_THETA = 3.0
        contrib = h * h;
    }

    float reg = 0.0f;
    if (tid < KK) {
        float n2 = 0.0f;
        #pragma unroll
        for (int d = 0; d < DD; d++) {
            float v = m[tid * 33 + d];
            n2 = fmaf(v, v, n2);
        }
        reg = sqrtf(n2);
    }

    red[tid] = contrib * (1.0f / (KK * (KK - 1))) + 0.001f * reg * (1.0f / KK);
    __syncthreads();
    for (int off = 128; off; off >>= 1) {
        if (tid < off) red[tid] += red[tid + off];
        __syncthreads();
    }
    if (tid == 0) atomicAdd(out, red[0] * (1.0f / BB));
}

// ---------------------------------------------------------------------------
// Pass 2: per-pixel hinge variance loss, folded directly into the scalar.
// One float4 (4 consecutive pixels) per thread; batched LDG.128s.
// ---------------------------------------------------------------------------
__global__ __launch_bounds__(P2_TPB) void k_pass2(const float* __restrict__ emb,
                                                  const int* __restrict__ gt,
                                                  float* out) {
    __shared__ float m[KK * 33];
    __shared__ float wk[KK];
    __shared__ float red[P2_TPB / 32];

    const int b  = blockIdx.y;
    const int tid = threadIdx.x;
    const int lane = tid & 31;
    const int w = tid >> 5;
    const int p4 = blockIdx.x * P2_TPB + tid;    // float4 index

    for (int j = tid; j < KK * DD; j += P2_TPB)
        m[(j / DD) * 33 + (j % DD)] = g_means[b * KK * DD + j];
    if (tid < KK)
        wk[tid] = 1.0f / ((float)KK * fmaxf(g_counts[b * KK + tid], 1.0f));
    __syncthreads();

    const float4* e4 = (const float4*)(emb + (size_t)b * DD * NPIX);
    const int4 kk = ((const int4*)(gt + (size_t)b * NPIX))[p4];

    const float* m0 = m + kk.x * 33;
    const float* m1 = m + kk.y * 33;
    const float* m2 = m + kk.z * 33;
    const float* m3 = m + kk.w * 33;

    float a0 = 0.0f, a1 = 0.0f, a2 = 0.0f, a3 = 0.0f;
    #pragma unroll
    for (int g = 0; g < 4; g++) {
        float4 v[8];
        #pragma unroll
        for (int j = 0; j < 8; j++)
            v[j] = __ldcs(&e4[(size_t)(g * 8 + j) * (NPIX / 4) + p4]);
        #pragma unroll
        for (int j = 0; j < 8; j++) {
            const int d = g * 8 + j;
            float t;
            t = v[j].x - m0[d]; a0 = fmaf(t, t, a0);
            t = v[j].y - m1[d]; a1 = fmaf(t, t, a1);
            t = v[j].z - m2[d]; a2 = fmaf(t, t, a2);
            t = v[j].w - m3[d]; a3 = fmaf(t, t, a3);
        }
    }

    float h, lacc = 0.0f;
    h = fmaxf(sqrtf(a0) - 0.5f, 0.0f); lacc = fmaf(h * h, wk[kk.x], lacc);
    h = fmaxf(sqrtf(a1) - 0.5f, 0.0f); lacc = fmaf(h * h, wk[kk.y], lacc);
    h = fmaxf(sqrtf(a2) - 0.5f, 0.0f); lacc = fmaf(h * h, wk[kk.z], lacc);
    h = fmaxf(sqrtf(a3) - 0.5f, 0.0f); lacc = fmaf(h * h, wk[kk.w], lacc);

    #pragma unroll
    for (int off = 16; off; off >>= 1)
        lacc += __shfl_down_sync(0xffffffffu, lacc, off);
    if (lane == 0) red[w] = lacc;
    __syncthreads();
    if (tid == 0) {
        float s = 0.0f;
        #pragma unroll
        for (int i = 0; i < P2_TPB / 32; i++) s += red[i];
        atomicAdd(out, s * (1.0f / BB));
    }
}

// ---------------------------------------------------------------------------
extern "C" void kernel_launch(void* const* d_in, const int* in_sizes, int n_in,
                              void* d_out, int out_size) {
    int ei = 0, gi = 1;
    // Defensive: identify inputs by size (embeddings = 67108864, gt = 2097152)
    if (n_in >= 2 && in_sizes[0] == BB * NPIX) { ei = 1; gi = 0; }

    const float* emb = (const float*)d_in[ei];
    const int*   gt  = (const int*)d_in[gi];
    float* out = (float*)d_out;

    k_pass1<<<dim3(P1_NCHUNK, 2, BB), 512>>>(emb, gt, out);
    k_finalize<<<BB, 256>>>(out);
    k_pass2<<<dim3(P2_BLOCKS, BB), P2_TPB>>>(emb, gt, out);
}

// round 5
// speedup vs baseline: 1.1502x; 1.0106x over previous
#include <cuda_runtime.h>
#include <cstddef>

// Problem constants (fixed by the reference)
#define BB 8
#define DD 32
#define NPIX 262144          // 512*512
#define KK 16

// Pass-1 tiling: 32 pixel-chunks x 2 d-groups x 8 images = 512 blocks
#define P1_CHUNK  8192
#define P1_NCHUNK (NPIX / P1_CHUNK)    // 32

// Pass-2 tiling: one float4 (4 pixels) per thread
#define P2_TPB    256
#define P2_BLOCKS (NPIX / 4 / P2_TPB)  // 256 blocks per image

// Scratch (no cudaMalloc allowed). Partials fully overwritten each launch.
__device__ float g_part[BB * P1_NCHUNK * KK * DD];   // per-chunk partial sums
__device__ float g_cntp[BB * P1_NCHUNK * KK];        // per-chunk partial counts
__device__ float g_counts[BB * KK];
__device__ float g_means[BB * KK * DD];

// ---------------------------------------------------------------------------
// Pass 1: per-image, per-chunk partial segment sums.
// Block = 512 threads = 16 warps; warp w owns plane d = dg*16 + w over the
// whole 8192-px chunk. Each lane batches FOUR independent LDG.128s per
// iteration (MLP=4) before the smem RMW burst.
// Per-lane privatized smem bins (stride 32): LDS/FADD/STS conflict-free.
// ---------------------------------------------------------------------------
__global__ __launch_bounds__(512) void k_pass1(const float* __restrict__ emb,
                                               const int* __restrict__ gt,
                                               float* out) {
    __shared__ float acc[16 * KK * 32];          // [w][k][lane]  32 KB
    __shared__ float cnt[KK * 32];               // [k][lane]      2 KB
    __shared__ uchar4 lab4[P1_CHUNK / 4];        //                8 KB

    const int b  = blockIdx.z;
    const int dg = blockIdx.y;                   // d group: 0 or 1
    const int c  = blockIdx.x;                   // chunk
    const int p0 = c * P1_CHUNK;
    const int tid = threadIdx.x;
    const int w   = tid >> 5;
    const int lane = tid & 31;
    const int d = dg * 16 + w;

    if (b == 0 && dg == 0 && c == 0 && tid == 0) out[0] = 0.0f;

    for (int j = tid; j < 16 * KK * 32; j += 512) acc[j] = 0.0f;
    if (tid < KK * 32) cnt[tid] = 0.0f;

    // Stage labels once (int4 -> uchar4): 2048 entries
    const int4* g4 = (const int4*)(gt + (size_t)b * NPIX + p0);
    for (int j = tid; j < P1_CHUNK / 4; j += 512) {
        int4 t = g4[j];
        lab4[j] = make_uchar4((unsigned char)t.x, (unsigned char)t.y,
                              (unsigned char)t.z, (unsigned char)t.w);
    }
    __syncthreads();

    const float4* e4 = (const float4*)(emb + ((size_t)(b * DD + d)) * NPIX + p0);
    const bool docnt = (dg == 0) && (w == 0);

    float* aw = acc + (w * KK) * 32 + lane;
    float* cw = cnt + lane;

    // 2048 float4s per plane-chunk per warp; 64 per lane, FOUR per iteration.
    #pragma unroll 1
    for (int i = 0; i < 16; i++) {
        const int idx = i * 128 + lane;
        float4 v0 = __ldcs(&e4[idx]);
        float4 v1 = __ldcs(&e4[idx + 32]);
        float4 v2 = __ldcs(&e4[idx + 64]);
        float4 v3 = __ldcs(&e4[idx + 96]);
        uchar4 c0 = lab4[idx];
        uchar4 c1 = lab4[idx + 32];
        uchar4 c2 = lab4[idx + 64];
        uchar4 c3 = lab4[idx + 96];

        aw[(int)c0.x * 32] += v0.x;
        aw[(int)c0.y * 32] += v0.y;
        aw[(int)c0.z * 32] += v0.z;
        aw[(int)c0.w * 32] += v0.w;
        aw[(int)c1.x * 32] += v1.x;
        aw[(int)c1.y * 32] += v1.y;
        aw[(int)c1.z * 32] += v1.z;
        aw[(int)c1.w * 32] += v1.w;
        aw[(int)c2.x * 32] += v2.x;
        aw[(int)c2.y * 32] += v2.y;
        aw[(int)c2.z * 32] += v2.z;
        aw[(int)c2.w * 32] += v2.w;
        aw[(int)c3.x * 32] += v3.x;
        aw[(int)c3.y * 32] += v3.y;
        aw[(int)c3.z * 32] += v3.z;
        aw[(int)c3.w * 32] += v3.w;

        if (docnt) {
            cw[(int)c0.x * 32] += 1.0f;
            cw[(int)c0.y * 32] += 1.0f;
            cw[(int)c0.z * 32] += 1.0f;
            cw[(int)c0.w * 32] += 1.0f;
            cw[(int)c1.x * 32] += 1.0f;
            cw[(int)c1.y * 32] += 1.0f;
            cw[(int)c1.z * 32] += 1.0f;
            cw[(int)c1.w * 32] += 1.0f;
            cw[(int)c2.x * 32] += 1.0f;
            cw[(int)c2.y * 32] += 1.0f;
            cw[(int)c2.z * 32] += 1.0f;
            cw[(int)c2.w * 32] += 1.0f;
            cw[(int)c3.x * 32] += 1.0f;
            cw[(int)c3.y * 32] += 1.0f;
            cw[(int)c3.z * 32] += 1.0f;
            cw[(int)c3.w * 32] += 1.0f;
        }
    }
    __syncwarp();

    // Epilogue: rows acc[w][k][0..31] are contiguous 128B. 2 lanes per k-row,
    // each reads 4 float4, sum, 1 shuffle, STG (no atomics).
    {
        const int k = lane >> 1;
        const int h = lane & 1;
        const float4* row = (const float4*)(acc + ((w * KK + k) << 5) + (h << 4));
        float4 r0 = row[0], r1 = row[1], r2 = row[2], r3 = row[3];
        float s = ((r0.x + r0.y) + (r0.z + r0.w)) + ((r1.x + r1.y) + (r1.z + r1.w))
                + ((r2.x + r2.y) + (r2.z + r2.w)) + ((r3.x + r3.y) + (r3.z + r3.w));
        s += __shfl_down_sync(0xffffffffu, s, 1);
        if (h == 0)
            g_part[(((b * P1_NCHUNK + c) * KK + k) * DD) + d] = s;
    }
    if (docnt) {
        const int k = lane >> 1;
        const int h = lane & 1;
        const float4* row = (const float4*)(cnt + (k << 5) + (h << 4));
        float4 r0 = row[0], r1 = row[1], r2 = row[2], r3 = row[3];
        float s = ((r0.x + r0.y) + (r0.z + r0.w)) + ((r1.x + r1.y) + (r1.z + r1.w))
                + ((r2.x + r2.y) + (r2.z + r2.w)) + ((r3.x + r3.y) + (r3.z + r3.w));
        s += __shfl_down_sync(0xffffffffu, s, 1);
        if (h == 0)
            g_cntp[(b * P1_NCHUNK + c) * KK + k] = s;
    }
}

// ---------------------------------------------------------------------------
// Finalize: reduce partials -> counts & means; pairwise push loss; reg loss.
// One block per image.
// ---------------------------------------------------------------------------
__global__ __launch_bounds__(256) void k_finalize(float* out) {
    __shared__ float m[KK * 33];    // padded means
    __shared__ float cs[KK];
    __shared__ float red[256];

    const int b = blockIdx.x;
    const int tid = threadIdx.x;

    if (tid < KK) {
        float s = 0.0f;
        #pragma unroll 4
        for (int c = 0; c < P1_NCHUNK; c++)
            s += g_cntp[(b * P1_NCHUNK + c) * KK + tid];
        float cv = fmaxf(s, 1.0f);
        cs[tid] = cv;
        g_counts[b * KK + tid] = cv;
    }
    __syncthreads();

    for (int j = tid; j < KK * DD; j += 256) {
        int k = j >> 5, d = j & 31;
        float s = 0.0f;
        #pragma unroll 4
        for (int c = 0; c < P1_NCHUNK; c++)
            s += g_part[(((b * P1_NCHUNK + c) * KK + k) * DD) + d];
        float mean = s / cs[k];
        g_means[(b * KK + k) * DD + d] = mean;
        m[k * 33 + d] = mean;
    }
    __syncthreads();

    // Pairwise hinge on cluster-mean distances: thread -> (i,j), upper tri only.
    const int i = tid >> 4;
    const int j = tid & 15;
    float contrib = 0.0f;
    if (j > i) {
        float d2 = 0.0f;
        #pragma unroll
        for (int d = 0; d < DD; d++) {
            float df = m[i * 33 + d] - m[j * 33 + d];
            d2 = fmaf(df, df, d2);
        }
        float pd = sqrtf(d2);             // i<j: diagonal eye irrelevant
        float h = fmaxf(3.0f - pd, 0.0f); // 2 * DIST_THETA = 3.0
        contrib = h * h;
    }

    float reg = 0.0f;
    if (tid < KK) {
        float n2 = 0.0f;
        #pragma unroll
        for (int d = 0; d < DD; d++) {
            float v = m[tid * 33 + d];
            n2 = fmaf(v, v, n2);
        }
        reg = sqrtf(n2);
    }

    red[tid] = contrib * (1.0f / (KK * (KK - 1))) + 0.001f * reg * (1.0f / KK);
    __syncthreads();
    for (int off = 128; off; off >>= 1) {
        if (tid < off) red[tid] += red[tid + off];
        __syncthreads();
    }
    if (tid == 0) atomicAdd(out, red[0] * (1.0f / BB));
}

// ---------------------------------------------------------------------------
// Pass 2: per-pixel hinge variance loss, folded directly into the scalar.
// One float4 (4 consecutive pixels) per thread; batched LDG.128s.
// ---------------------------------------------------------------------------
__global__ __launch_bounds__(P2_TPB) void k_pass2(const float* __restrict__ emb,
                                                  const int* __restrict__ gt,
                                                  float* out) {
    __shared__ float m[KK * 33];
    __shared__ float wk[KK];
    __shared__ float red[P2_TPB / 32];

    const int b  = blockIdx.y;
    const int tid = threadIdx.x;
    const int lane = tid & 31;
    const int w = tid >> 5;
    const int p4 = blockIdx.x * P2_TPB + tid;    // float4 index

    for (int j = tid; j < KK * DD; j += P2_TPB)
        m[(j / DD) * 33 + (j % DD)] = g_means[b * KK * DD + j];
    if (tid < KK)
        wk[tid] = 1.0f / ((float)KK * fmaxf(g_counts[b * KK + tid], 1.0f));
    __syncthreads();

    const float4* e4 = (const float4*)(emb + (size_t)b * DD * NPIX);
    const int4 kk = ((const int4*)(gt + (size_t)b * NPIX))[p4];

    const float* m0 = m + kk.x * 33;
    const float* m1 = m + kk.y * 33;
    const float* m2 = m + kk.z * 33;
    const float* m3 = m + kk.w * 33;

    float a0 = 0.0f, a1 = 0.0f, a2 = 0.0f, a3 = 0.0f;
    #pragma unroll
    for (int g = 0; g < 4; g++) {
        float4 v[8];
        #pragma unroll
        for (int j = 0; j < 8; j++)
            v[j] = __ldcs(&e4[(size_t)(g * 8 + j) * (NPIX / 4) + p4]);
        #pragma unroll
        for (int j = 0; j < 8; j++) {
            const int d = g * 8 + j;
            float t;
            t = v[j].x - m0[d]; a0 = fmaf(t, t, a0);
            t = v[j].y - m1[d]; a1 = fmaf(t, t, a1);
            t = v[j].z - m2[d]; a2 = fmaf(t, t, a2);
            t = v[j].w - m3[d]; a3 = fmaf(t, t, a3);
        }
    }

    float h, lacc = 0.0f;
    h = fmaxf(sqrtf(a0) - 0.5f, 0.0f); lacc = fmaf(h * h, wk[kk.x], lacc);
    h = fmaxf(sqrtf(a1) - 0.5f, 0.0f); lacc = fmaf(h * h, wk[kk.y], lacc);
    h = fmaxf(sqrtf(a2) - 0.5f, 0.0f); lacc = fmaf(h * h, wk[kk.z], lacc);
    h = fmaxf(sqrtf(a3) - 0.5f, 0.0f); lacc = fmaf(h * h, wk[kk.w], lacc);

    #pragma unroll
    for (int off = 16; off; off >>= 1)
        lacc += __shfl_down_sync(0xffffffffu, lacc, off);
    if (lane == 0) red[w] = lacc;
    __syncthreads();
    if (tid == 0) {
        float s = 0.0f;
        #pragma unroll
        for (int i = 0; i < P2_TPB / 32; i++) s += red[i];
        atomicAdd(out, s * (1.0f / BB));
    }
}

// ---------------------------------------------------------------------------
extern "C" void kernel_launch(void* const* d_in, const int* in_sizes, int n_in,
                              void* d_out, int out_size) {
    int ei = 0, gi = 1;
    // Defensive: identify inputs by size (embeddings = 67108864, gt = 2097152)
    if (n_in >= 2 && in_sizes[0] == BB * NPIX) { ei = 1; gi = 0; }

    const float* emb = (const float*)d_in[ei];
    const int*   gt  = (const int*)d_in[gi];
    float* out = (float*)d_out;

    k_pass1<<<dim3(P1_NCHUNK, 2, BB), 512>>>(emb, gt, out);
    k_finalize<<<BB, 256>>>(out);
    k_pass2<<<dim3(P2_BLOCKS, BB), P2_TPB>>>(emb, gt, out);
}